// round 12
// baseline (speedup 1.0000x reference)
#include <cuda_runtime.h>
#include <cuda_bf16.h>
#include <math.h>
#include <stdint.h>

// Problem dims (fixed by the dataset)
#define B_  64
#define S_  1024
#define I_  1024
#define H_  1024

// =================== base-ISA PTX helpers (no sm_103a-only features) ===========
__device__ __forceinline__ uint32_t smem_u32(const void* p) {
    uint32_t a;
    asm("{ .reg .u64 t; cvta.to.shared.u64 t, %1; cvt.u32.u64 %0, t; }"
        : "=r"(a) : "l"(p));
    return a;
}
__device__ __forceinline__ void cp_async16(uint32_t saddr, const void* gaddr) {
    asm volatile("cp.async.cg.shared.global [%0], [%1], 16;"
                 :: "r"(saddr), "l"(gaddr));
}
__device__ __forceinline__ void cp_commit() {
    asm volatile("cp.async.commit_group;" ::: "memory");
}
template <int N>
__device__ __forceinline__ void cp_wait() {
    asm volatile("cp.async.wait_group %0;" :: "n"(N) : "memory");
}
__device__ __forceinline__ void ldsm4(uint32_t* r, uint32_t a) {
    asm volatile("ldmatrix.sync.aligned.m8n8.x4.shared.b16 {%0,%1,%2,%3}, [%4];"
                 : "=r"(r[0]), "=r"(r[1]), "=r"(r[2]), "=r"(r[3]) : "r"(a));
}
__device__ __forceinline__ void ldsm2(uint32_t* r, uint32_t a) {
    asm volatile("ldmatrix.sync.aligned.m8n8.x2.shared.b16 {%0,%1}, [%2];"
                 : "=r"(r[0]), "=r"(r[1]) : "r"(a));
}
// D(f32) += A(bf16) * B(bf16)^T, m16n8k16
__device__ __forceinline__ void mma16816(float* c, const uint32_t* a, const uint32_t* b) {
    asm volatile(
        "mma.sync.aligned.m16n8k16.row.col.f32.bf16.bf16.f32 "
        "{%0,%1,%2,%3}, {%4,%5,%6,%7}, {%8,%9}, {%0,%1,%2,%3};"
        : "+f"(c[0]), "+f"(c[1]), "+f"(c[2]), "+f"(c[3])
        : "r"(a[0]), "r"(a[1]), "r"(a[2]), "r"(a[3]), "r"(b[0]), "r"(b[1]));
}
#define BAR_PAIR(id) asm volatile("bar.sync %0, %1;" :: "r"(id), "r"(64) : "memory")

// =================== persistent state (no allocations allowed) ===================
// two-level grid barrier
__device__ unsigned          g_cnt[8 * 32];   // 8 group counters, line-padded
__device__ unsigned          g_root;
__device__ volatile unsigned g_epoch;
// hidden state ping-pong, bf16 hi/lo split, TILED layout:
//   elem (b,k) at (k>>4)*1024 + b*16 + (k&15)   (i.e. [k/16][b][16])
__device__ __nv_bfloat16 g_hb[2][2][B_ * H_];
// bf16-split scratch for phase-1 tensor-core GEMM
__device__ __nv_bfloat16 g_xhi[(size_t)B_ * S_ * I_];
__device__ __nv_bfloat16 g_xlo[(size_t)B_ * S_ * I_];
__device__ __nv_bfloat16 g_whi[(size_t)H_ * I_];
__device__ __nv_bfloat16 g_wlo[(size_t)H_ * I_];

// =================== init: h0 -> tiled bf16 hi/lo, reset barrier =========
__global__ void init_kernel(const float* __restrict__ h0) {
    int i = blockIdx.x * blockDim.x + threadIdx.x;
    if (i < B_ * H_) {
        int b = i >> 10, k = i & 1023;
        float v = h0[i];
        __nv_bfloat16 h = __float2bfloat16(v);
        __nv_bfloat16 l = __float2bfloat16(v - __bfloat162float(h));
        int idx = (k >> 4) * 1024 + b * 16 + (k & 15);
        g_hb[0][0][idx] = h;
        g_hb[0][1][idx] = l;
    }
    if (i < 8 * 32) g_cnt[i] = 0u;
    if (i == 0) { g_root = 0u; g_epoch = 0u; }
}

// =================== fp32 -> (hi, lo) bf16 split (x, Wih) ===================
__global__ void convert_x_kernel(const float* __restrict__ src) {
    size_t i = (size_t)blockIdx.x * blockDim.x + threadIdx.x;   // one float4
    float4 v = ((const float4*)src)[i];
    __nv_bfloat16 hx = __float2bfloat16(v.x), hy = __float2bfloat16(v.y);
    __nv_bfloat16 hz = __float2bfloat16(v.z), hw = __float2bfloat16(v.w);
    __nv_bfloat16 lx = __float2bfloat16(v.x - __bfloat162float(hx));
    __nv_bfloat16 ly = __float2bfloat16(v.y - __bfloat162float(hy));
    __nv_bfloat16 lz = __float2bfloat16(v.z - __bfloat162float(hz));
    __nv_bfloat16 lw = __float2bfloat16(v.w - __bfloat162float(hw));
    __nv_bfloat162* dh = ((__nv_bfloat162*)g_xhi) + 2 * i;
    __nv_bfloat162* dl = ((__nv_bfloat162*)g_xlo) + 2 * i;
    dh[0] = __halves2bfloat162(hx, hy); dh[1] = __halves2bfloat162(hz, hw);
    dl[0] = __halves2bfloat162(lx, ly); dl[1] = __halves2bfloat162(lz, lw);
}
__global__ void convert_w_kernel(const float* __restrict__ src) {
    size_t i = (size_t)blockIdx.x * blockDim.x + threadIdx.x;
    float4 v = ((const float4*)src)[i];
    __nv_bfloat16 hx = __float2bfloat16(v.x), hy = __float2bfloat16(v.y);
    __nv_bfloat16 hz = __float2bfloat16(v.z), hw = __float2bfloat16(v.w);
    __nv_bfloat16 lx = __float2bfloat16(v.x - __bfloat162float(hx));
    __nv_bfloat16 ly = __float2bfloat16(v.y - __bfloat162float(hy));
    __nv_bfloat16 lz = __float2bfloat16(v.z - __bfloat162float(hz));
    __nv_bfloat16 lw = __float2bfloat16(v.w - __bfloat162float(hw));
    __nv_bfloat162* dh = ((__nv_bfloat162*)g_whi) + 2 * i;
    __nv_bfloat162* dl = ((__nv_bfloat162*)g_wlo) + 2 * i;
    dh[0] = __halves2bfloat162(hx, hy); dh[1] = __halves2bfloat162(hz, hw);
    dl[0] = __halves2bfloat162(lx, ly); dl[1] = __halves2bfloat162(lz, lw);
}

// =================== Phase 1: mma.sync bf16-split GEMM (proven R8) ==============
#define BKE   16
#define LDT   24
#define TILE_E (128 * LDT)          // 3072 elems = 6144 B
#define NKC   (I_ / BKE)            // 64

__global__ __launch_bounds__(256) void gemm_wx_mma(const float* __restrict__ bias,
                                                   float* __restrict__ C) {
    __shared__ __nv_bfloat16 stg[2][4][TILE_E];   // 49152 B

    const int tid = threadIdx.x;
    const int wid = tid >> 5, lid = tid & 31;
    const int wm = wid >> 2, wn = wid & 3;        // 2 x 4 warps
    const int m0 = blockIdx.y * 128, n0 = blockIdx.x * 128;
    const uint32_t sb = smem_u32(stg);

    const int ltile = tid >> 6;                   // 0..3
    const int lrow2 = (tid & 63) * 2;

    const int grp = lid >> 3, li8 = lid & 7;
    uint32_t offA[4], offB[4];
    #pragma unroll
    for (int f = 0; f < 4; f++)
        offA[f] = (uint32_t)((wm * 64 + f * 16 + li8 + (grp & 1) * 8) * 48 + (grp >> 1) * 16);
    #pragma unroll
    for (int nf = 0; nf < 4; nf++)
        offB[nf] = (uint32_t)((wn * 32 + nf * 8 + li8) * 48 + (grp & 1) * 16);

    float acc[4][4][4];
    #pragma unroll
    for (int f = 0; f < 4; f++)
        #pragma unroll
        for (int nf = 0; nf < 4; nf++)
            #pragma unroll
            for (int q = 0; q < 4; q++) acc[f][nf][q] = 0.f;

    auto load_stage = [&](int kc, int s) {
        const int koff = kc * BKE;
        #pragma unroll
        for (int i = 0; i < 4; i++) {
            const int row = lrow2 + (i >> 1), seg = i & 1;
            const __nv_bfloat16* gp;
            if      (ltile == 0) gp = g_xhi + (size_t)(m0 + row) * I_ + koff + seg * 8;
            else if (ltile == 1) gp = g_xlo + (size_t)(m0 + row) * I_ + koff + seg * 8;
            else if (ltile == 2) gp = g_whi + (size_t)(n0 + row) * I_ + koff + seg * 8;
            else                 gp = g_wlo + (size_t)(n0 + row) * I_ + koff + seg * 8;
            uint32_t sa = sb + (uint32_t)(((s * 4 + ltile) * TILE_E + row * LDT + seg * 8) * 2);
            cp_async16(sa, gp);
        }
        cp_commit();
    };

    load_stage(0, 0);

    for (int kc = 0; kc < NKC; kc++) {
        const int s = kc & 1;
        if (kc + 1 < NKC) { load_stage(kc + 1, s ^ 1); cp_wait<1>(); }
        else             { cp_wait<0>(); }
        __syncthreads();

        const uint32_t base = sb + (uint32_t)(s * 4 * TILE_E * 2);
        const uint32_t tAh = base, tAl = base + 6144, tBh = base + 12288, tBl = base + 18432;

        uint32_t Ah[4][4], Al[4][4], Bh[4][2], Bl[4][2];
        #pragma unroll
        for (int f = 0; f < 4; f++) { ldsm4(Ah[f], tAh + offA[f]); ldsm4(Al[f], tAl + offA[f]); }
        #pragma unroll
        for (int nf = 0; nf < 4; nf++) { ldsm2(Bh[nf], tBh + offB[nf]); ldsm2(Bl[nf], tBl + offB[nf]); }

        #pragma unroll
        for (int f = 0; f < 4; f++)
            #pragma unroll
            for (int nf = 0; nf < 4; nf++) {
                mma16816(acc[f][nf], Ah[f], Bh[nf]);
                mma16816(acc[f][nf], Ah[f], Bl[nf]);
                mma16816(acc[f][nf], Al[f], Bh[nf]);
            }
        __syncthreads();
    }

    #pragma unroll
    for (int nf = 0; nf < 4; nf++) {
        const int col = n0 + wn * 32 + nf * 8 + (lid & 3) * 2;
        const float bx = bias[col], by = bias[col + 1];
        #pragma unroll
        for (int f = 0; f < 4; f++) {
            const size_t r0 = (size_t)(m0 + wm * 64 + f * 16 + (lid >> 2));
            float* cp = C + r0 * H_ + col;
            float2 v0 = make_float2(acc[f][nf][0] + bx, acc[f][nf][1] + by);
            float2 v1 = make_float2(acc[f][nf][2] + bx, acc[f][nf][3] + by);
            *(float2*)cp = v0;
            *(float2*)(cp + (size_t)8 * H_) = v1;
        }
    }
}

// =================== Phase 2: tensor-core persistent scan, per-pair pipelines ===
// 64 CTAs; CTA owns 16 output cols (Whh slice bf16 hi/lo resident, R9 layout).
// 8 warps = 4 m-pairs x 2 n-warps. Each 64-thread pair owns batches [p*16,p*16+16)
// with private 2-deep cp.async staging and named barriers -> 4 independent
// pipelines per SM. Full K per fragment, 3-pass split MMA (hh+hl+lh).
#define SC_NCTA 64
#define SC_NC   16
#define SC_T    256
#define SC_WB    49152                  // one W array: 64 kc x 16 rows x 24 x 2B
#define SC_AOFF  (2 * SC_WB)            // 98304
#define SC_PAIRB 24576                  // per pair: 2 bufs x (hi 6144 + lo 6144)
#define SC_BUFB  12288
#define SC_SMEM  (SC_AOFF + 4 * SC_PAIRB)   // 196608

__global__ __launch_bounds__(SC_T) void rnn_tc2_kernel(
    const float* __restrict__ Whh,
    const float* __restrict__ Whh_b,
    float* __restrict__ y,      // [B,S,H], contains wx on entry
    float* __restrict__ hlast)  // [B,H] or nullptr
{
    extern __shared__ __nv_bfloat16 sm[];
    const uint32_t smb = smem_u32(sm);

    const int tid = threadIdx.x;
    const int wid = tid >> 5, lid = tid & 31;
    const int p  = wid >> 1;            // pair 0..3 (batch slice)
    const int wn = wid & 1;             // n8 half
    const int ptid = tid & 63;          // thread within pair
    const int cta = blockIdx.x;
    const int g0 = cta * SC_NC;
    const int grpid = cta >> 3;         // barrier group

    // ---- load + split this CTA's Whh slice into tiled smem (once; R9-proven) ----
    __nv_bfloat16* sWhi = sm;
    __nv_bfloat16* sWlo = sm + SC_WB / 2;
    for (int idx = tid; idx < SC_NC * H_; idx += SC_T) {
        int gr = idx >> 10, k = idx & 1023;
        float v = Whh[(size_t)(g0 + gr) * H_ + k];
        __nv_bfloat16 h = __float2bfloat16(v);
        __nv_bfloat16 l = __float2bfloat16(v - __bfloat162float(h));
        int si = ((k >> 4) * SC_NC + gr) * LDT + (k & 15);
        sWhi[si] = h; sWlo[si] = l;
    }
    __syncthreads();

    // fragment lane offsets (proven geometry)
    const int grp = lid >> 3, li8 = lid & 7;
    const uint32_t offA  = (uint32_t)((li8 + (grp & 1) * 8) * 48 + (grp >> 1) * 16);
    const uint32_t offB4 = (uint32_t)((wn * 8 + li8) * 48 + (grp & 1) * 16 + (grp >> 1) * 768);

    // epilogue lane geometry
    const int b_r0 = p * 16 + (lid >> 2);
    const int b_r1 = b_r0 + 8;
    const int gc   = g0 + wn * 8 + (lid & 3) * 2;
    const float bi0 = Whh_b[gc], bi1 = Whh_b[gc + 1];

    const uint32_t abase = smb + SC_AOFF + (uint32_t)(p * SC_PAIRB);

    for (int t = 0; t < S_; t++) {
        const __nv_bfloat16* hbhi = g_hb[t & 1][0];
        const __nv_bfloat16* hblo = g_hb[t & 1][1];
        __nv_bfloat16* hnhi = g_hb[(t & 1) ^ 1][0];
        __nv_bfloat16* hnlo = g_hb[(t & 1) ^ 1][1];

        // prefetch wx (independent of h; latency hidden by stage loop)
        float2 wx0 = *(const float2*)&y[((size_t)b_r0 * S_ + t) * H_ + gc];
        float2 wx1 = *(const float2*)&y[((size_t)b_r1 * S_ + t) * H_ + gc];

        // per-pair stage issue: 8 cp.async16 per thread = 8KB stage (hi+lo)
        auto issue = [&](int st, int buf) {
            #pragma unroll
            for (int i = 0; i < 8; i++) {
                int v   = ptid * 8 + i;       // 0..511
                int hl  = v >> 8;             // 0: hi, 1: lo
                int rem = v & 255;
                int kb  = rem >> 5;           // 0..7
                int row = (rem >> 1) & 15;    // batch within pair
                int s   = rem & 1;
                const __nv_bfloat16* src = (hl ? hblo : hbhi)
                    + ((size_t)(st * 8 + kb) * 64 + (p * 16 + row)) * 16 + s * 8;
                uint32_t dst = abase + (uint32_t)(buf * SC_BUFB + hl * 6144
                               + (kb * 16 + row) * 48 + s * 16);
                cp_async16(dst, src);
            }
            cp_commit();
        };

        issue(0, 0);
        issue(1, 1);

        float a0[4] = {0.f, 0.f, 0.f, 0.f};
        float a1[4] = {0.f, 0.f, 0.f, 0.f};
        float a2[4] = {0.f, 0.f, 0.f, 0.f};

        #pragma unroll 1
        for (int st = 0; st < 8; st++) {
            if (st == 7) cp_wait<0>(); else cp_wait<1>();
            BAR_PAIR(1 + p);                       // stage data ready (pair-wide)
            const uint32_t Ah_b = abase + (uint32_t)((st & 1) * SC_BUFB);
            const uint32_t Al_b = Ah_b + 6144;
            #pragma unroll
            for (int kb = 0; kb < 8; kb += 2) {
                const int kc = st * 8 + kb;
                uint32_t B4h[4], B4l[4];
                ldsm4(B4h, smb + (uint32_t)(kc * 768) + offB4);
                ldsm4(B4l, smb + SC_WB + (uint32_t)(kc * 768) + offB4);
                #pragma unroll
                for (int j = 0; j < 2; j++) {
                    uint32_t Ah[4], Al[4];
                    ldsm4(Ah, Ah_b + (uint32_t)((kb + j) * 768) + offA);
                    ldsm4(Al, Al_b + (uint32_t)((kb + j) * 768) + offA);
                    mma16816(a0, Ah, B4h + 2 * j);
                    mma16816(a1, Ah, B4l + 2 * j);
                    mma16816(a2, Al, B4h + 2 * j);
                }
            }
            if (st + 2 < 8) {
                BAR_PAIR(1 + p);                   // both warps done with this buffer
                issue(st + 2, st & 1);
            }
        }

        // epilogue: tanh(wx + bias + sum), write y + split-bf16 h_next
        float v00 = tanhf(wx0.x + bi0 + (a0[0] + a1[0] + a2[0]));
        float v01 = tanhf(wx0.y + bi1 + (a0[1] + a1[1] + a2[1]));
        float v10 = tanhf(wx1.x + bi0 + (a0[2] + a1[2] + a2[2]));
        float v11 = tanhf(wx1.y + bi1 + (a0[3] + a1[3] + a2[3]));

        *(float2*)&y[((size_t)b_r0 * S_ + t) * H_ + gc] = make_float2(v00, v01);
        *(float2*)&y[((size_t)b_r1 * S_ + t) * H_ + gc] = make_float2(v10, v11);

        {
            __nv_bfloat16 h00 = __float2bfloat16(v00), h01 = __float2bfloat16(v01);
            __nv_bfloat16 h10 = __float2bfloat16(v10), h11 = __float2bfloat16(v11);
            __nv_bfloat16 l00 = __float2bfloat16(v00 - __bfloat162float(h00));
            __nv_bfloat16 l01 = __float2bfloat16(v01 - __bfloat162float(h01));
            __nv_bfloat16 l10 = __float2bfloat16(v10 - __bfloat162float(h10));
            __nv_bfloat16 l11 = __float2bfloat16(v11 - __bfloat162float(h11));
            int idx0 = (gc >> 4) * 1024 + b_r0 * 16 + (gc & 15);
            int idx1 = (gc >> 4) * 1024 + b_r1 * 16 + (gc & 15);
            *(__nv_bfloat162*)&hnhi[idx0] = __halves2bfloat162(h00, h01);
            *(__nv_bfloat162*)&hnlo[idx0] = __halves2bfloat162(l00, l01);
            *(__nv_bfloat162*)&hnhi[idx1] = __halves2bfloat162(h10, h11);
            *(__nv_bfloat162*)&hnlo[idx1] = __halves2bfloat162(l10, l11);
        }

        if (hlast && t == S_ - 1) {
            *(float2*)&hlast[(size_t)b_r0 * H_ + gc] = make_float2(v00, v01);
            *(float2*)&hlast[(size_t)b_r1 * H_ + gc] = make_float2(v10, v11);
        }

        // ---- two-level grid barrier: group counters -> root -> epoch flag ----
        __threadfence();
        __syncthreads();
        if (tid == 0) {
            const unsigned tgt = 8u * (unsigned)(t + 1);
            unsigned old = atomicAdd(&g_cnt[grpid * 32], 1u);
            if (old == tgt - 1u) {                       // last arrival in group
                unsigned r = atomicAdd(&g_root, 1u);
                if (r == tgt - 1u) {                     // last group
                    __threadfence();
                    g_epoch = (unsigned)(t + 1);
                }
            }
            while (g_epoch < (unsigned)(t + 1)) { __nanosleep(32); }
            __threadfence();
        }
        __syncthreads();
    }
}

// =================== launch ===================
extern "C" void kernel_launch(void* const* d_in, const int* in_sizes, int n_in,
                              void* d_out, int out_size) {
    (void)in_sizes; (void)n_in;
    const float* x     = (const float*)d_in[0];
    const float* h0    = (const float*)d_in[1];
    const float* Wih_w = (const float*)d_in[2];
    const float* Wih_b = (const float*)d_in[3];
    const float* Whh_w = (const float*)d_in[4];
    const float* Whh_b = (const float*)d_in[5];

    float* out   = (float*)d_out;
    float* y     = out;
    float* hlast = nullptr;
    const long long ybsh = (long long)B_ * S_ * H_;
    if ((long long)out_size >= ybsh + (long long)B_ * H_)
        hlast = out + ybsh;

    cudaFuncSetAttribute(rnn_tc2_kernel, cudaFuncAttributeMaxDynamicSharedMemorySize,
                         SC_SMEM);

    // 1) init hidden state (tiled bf16 hi/lo) + barrier state
    init_kernel<<<(B_ * H_ + 255) / 256, 256>>>(h0);

    // 2) bf16 hi/lo split of x and Wih
    convert_x_kernel<<<(B_ * S_ * I_ / 4) / 256, 256>>>(x);
    convert_w_kernel<<<(H_ * I_ / 4) / 256, 256>>>(Wih_w);

    // 3) wx = x @ Wih^T + b via mma.sync bf16 split (3 passes), into y
    dim3 gg(H_ / 128, (B_ * S_) / 128);
    gemm_wx_mma<<<gg, 256>>>(Wih_b, y);

    // 4) tensor-core persistent recurrent scan (per-pair pipelines)
    rnn_tc2_kernel<<<SC_NCTA, SC_T, SC_SMEM>>>(Whh_w, Whh_b, y, hlast);
}

// round 15
// speedup vs baseline: 1.9839x; 1.9839x over previous
#include <cuda_runtime.h>
#include <cuda_bf16.h>
#include <math.h>
#include <stdint.h>

// Problem dims (fixed by the dataset)
#define B_  64
#define S_  1024
#define I_  1024
#define H_  1024

// =================== base-ISA PTX helpers (no sm_103a-only features) ===========
__device__ __forceinline__ uint32_t smem_u32(const void* p) {
    uint32_t a;
    asm("{ .reg .u64 t; cvta.to.shared.u64 t, %1; cvt.u32.u64 %0, t; }"
        : "=r"(a) : "l"(p));
    return a;
}
__device__ __forceinline__ void cp_async16(uint32_t saddr, const void* gaddr) {
    asm volatile("cp.async.cg.shared.global [%0], [%1], 16;"
                 :: "r"(saddr), "l"(gaddr));
}
__device__ __forceinline__ void cp_commit() {
    asm volatile("cp.async.commit_group;" ::: "memory");
}
template <int N>
__device__ __forceinline__ void cp_wait() {
    asm volatile("cp.async.wait_group %0;" :: "n"(N) : "memory");
}
__device__ __forceinline__ void ldsm4(uint32_t* r, uint32_t a) {
    asm volatile("ldmatrix.sync.aligned.m8n8.x4.shared.b16 {%0,%1,%2,%3}, [%4];"
                 : "=r"(r[0]), "=r"(r[1]), "=r"(r[2]), "=r"(r[3]) : "r"(a));
}
__device__ __forceinline__ void ldsm2(uint32_t* r, uint32_t a) {
    asm volatile("ldmatrix.sync.aligned.m8n8.x2.shared.b16 {%0,%1}, [%2];"
                 : "=r"(r[0]), "=r"(r[1]) : "r"(a));
}
// D(f32) += A(bf16) * B(bf16)^T, m16n8k16
__device__ __forceinline__ void mma16816(float* c, const uint32_t* a, const uint32_t* b) {
    asm volatile(
        "mma.sync.aligned.m16n8k16.row.col.f32.bf16.bf16.f32 "
        "{%0,%1,%2,%3}, {%4,%5,%6,%7}, {%8,%9}, {%0,%1,%2,%3};"
        : "+f"(c[0]), "+f"(c[1]), "+f"(c[2]), "+f"(c[3])
        : "r"(a[0]), "r"(a[1]), "r"(a[2]), "r"(a[3]), "r"(b[0]), "r"(b[1]));
}

// =================== persistent state (no allocations allowed) ===================
__device__ float    g_h[2][B_ * H_];   // ping-pong hidden state (fp32)
// two-level grid barrier (8 groups x 16 CTAs)
__device__ unsigned          g_cnt[8 * 32];   // group counters, line-padded
__device__ unsigned          g_root;
__device__ volatile unsigned g_epoch;
// bf16-split scratch for phase-1 tensor-core GEMM
__device__ __nv_bfloat16 g_xhi[(size_t)B_ * S_ * I_];
__device__ __nv_bfloat16 g_xlo[(size_t)B_ * S_ * I_];
__device__ __nv_bfloat16 g_whi[(size_t)H_ * I_];
__device__ __nv_bfloat16 g_wlo[(size_t)H_ * I_];

// =================== init: copy h0, reset barrier ===================
__global__ void init_kernel(const float* __restrict__ h0) {
    int i = blockIdx.x * blockDim.x + threadIdx.x;
    if (i < B_ * H_) g_h[0][i] = h0[i];
    if (i < 8 * 32) g_cnt[i] = 0u;
    if (i == 0) { g_root = 0u; g_epoch = 0u; }
}

// =================== fp32 -> (hi, lo) bf16 split (x, Wih) ===================
__global__ void convert_x_kernel(const float* __restrict__ src) {
    size_t i = (size_t)blockIdx.x * blockDim.x + threadIdx.x;   // one float4
    float4 v = ((const float4*)src)[i];
    __nv_bfloat16 hx = __float2bfloat16(v.x), hy = __float2bfloat16(v.y);
    __nv_bfloat16 hz = __float2bfloat16(v.z), hw = __float2bfloat16(v.w);
    __nv_bfloat16 lx = __float2bfloat16(v.x - __bfloat162float(hx));
    __nv_bfloat16 ly = __float2bfloat16(v.y - __bfloat162float(hy));
    __nv_bfloat16 lz = __float2bfloat16(v.z - __bfloat162float(hz));
    __nv_bfloat16 lw = __float2bfloat16(v.w - __bfloat162float(hw));
    __nv_bfloat162* dh = ((__nv_bfloat162*)g_xhi) + 2 * i;
    __nv_bfloat162* dl = ((__nv_bfloat162*)g_xlo) + 2 * i;
    dh[0] = __halves2bfloat162(hx, hy); dh[1] = __halves2bfloat162(hz, hw);
    dl[0] = __halves2bfloat162(lx, ly); dl[1] = __halves2bfloat162(lz, lw);
}
__global__ void convert_w_kernel(const float* __restrict__ src) {
    size_t i = (size_t)blockIdx.x * blockDim.x + threadIdx.x;
    float4 v = ((const float4*)src)[i];
    __nv_bfloat16 hx = __float2bfloat16(v.x), hy = __float2bfloat16(v.y);
    __nv_bfloat16 hz = __float2bfloat16(v.z), hw = __float2bfloat16(v.w);
    __nv_bfloat16 lx = __float2bfloat16(v.x - __bfloat162float(hx));
    __nv_bfloat16 ly = __float2bfloat16(v.y - __bfloat162float(hy));
    __nv_bfloat16 lz = __float2bfloat16(v.z - __bfloat162float(hz));
    __nv_bfloat16 lw = __float2bfloat16(v.w - __bfloat162float(hw));
    __nv_bfloat162* dh = ((__nv_bfloat162*)g_whi) + 2 * i;
    __nv_bfloat162* dl = ((__nv_bfloat162*)g_wlo) + 2 * i;
    dh[0] = __halves2bfloat162(hx, hy); dh[1] = __halves2bfloat162(hz, hw);
    dl[0] = __halves2bfloat162(lx, ly); dl[1] = __halves2bfloat162(lz, lw);
}

// =================== Phase 1: mma.sync bf16-split GEMM (proven R8) ==============
#define BKE   16
#define LDT   24
#define TILE_E (128 * LDT)          // 3072 elems = 6144 B
#define NKC   (I_ / BKE)            // 64

__global__ __launch_bounds__(256) void gemm_wx_mma(const float* __restrict__ bias,
                                                   float* __restrict__ C) {
    __shared__ __nv_bfloat16 stg[2][4][TILE_E];   // 49152 B

    const int tid = threadIdx.x;
    const int wid = tid >> 5, lid = tid & 31;
    const int wm = wid >> 2, wn = wid & 3;        // 2 x 4 warps
    const int m0 = blockIdx.y * 128, n0 = blockIdx.x * 128;
    const uint32_t sb = smem_u32(stg);

    const int ltile = tid >> 6;                   // 0..3
    const int lrow2 = (tid & 63) * 2;

    const int grp = lid >> 3, li8 = lid & 7;
    uint32_t offA[4], offB[4];
    #pragma unroll
    for (int f = 0; f < 4; f++)
        offA[f] = (uint32_t)((wm * 64 + f * 16 + li8 + (grp & 1) * 8) * 48 + (grp >> 1) * 16);
    #pragma unroll
    for (int nf = 0; nf < 4; nf++)
        offB[nf] = (uint32_t)((wn * 32 + nf * 8 + li8) * 48 + (grp & 1) * 16);

    float acc[4][4][4];
    #pragma unroll
    for (int f = 0; f < 4; f++)
        #pragma unroll
        for (int nf = 0; nf < 4; nf++)
            #pragma unroll
            for (int q = 0; q < 4; q++) acc[f][nf][q] = 0.f;

    auto load_stage = [&](int kc, int s) {
        const int koff = kc * BKE;
        #pragma unroll
        for (int i = 0; i < 4; i++) {
            const int row = lrow2 + (i >> 1), seg = i & 1;
            const __nv_bfloat16* gp;
            if      (ltile == 0) gp = g_xhi + (size_t)(m0 + row) * I_ + koff + seg * 8;
            else if (ltile == 1) gp = g_xlo + (size_t)(m0 + row) * I_ + koff + seg * 8;
            else if (ltile == 2) gp = g_whi + (size_t)(n0 + row) * I_ + koff + seg * 8;
            else                 gp = g_wlo + (size_t)(n0 + row) * I_ + koff + seg * 8;
            uint32_t sa = sb + (uint32_t)(((s * 4 + ltile) * TILE_E + row * LDT + seg * 8) * 2);
            cp_async16(sa, gp);
        }
        cp_commit();
    };

    load_stage(0, 0);

    for (int kc = 0; kc < NKC; kc++) {
        const int s = kc & 1;
        if (kc + 1 < NKC) { load_stage(kc + 1, s ^ 1); cp_wait<1>(); }
        else             { cp_wait<0>(); }
        __syncthreads();

        const uint32_t base = sb + (uint32_t)(s * 4 * TILE_E * 2);
        const uint32_t tAh = base, tAl = base + 6144, tBh = base + 12288, tBl = base + 18432;

        uint32_t Ah[4][4], Al[4][4], Bh[4][2], Bl[4][2];
        #pragma unroll
        for (int f = 0; f < 4; f++) { ldsm4(Ah[f], tAh + offA[f]); ldsm4(Al[f], tAl + offA[f]); }
        #pragma unroll
        for (int nf = 0; nf < 4; nf++) { ldsm2(Bh[nf], tBh + offB[nf]); ldsm2(Bl[nf], tBl + offB[nf]); }

        #pragma unroll
        for (int f = 0; f < 4; f++)
            #pragma unroll
            for (int nf = 0; nf < 4; nf++) {
                mma16816(acc[f][nf], Ah[f], Bh[nf]);
                mma16816(acc[f][nf], Ah[f], Bl[nf]);
                mma16816(acc[f][nf], Al[f], Bh[nf]);
            }
        __syncthreads();
    }

    #pragma unroll
    for (int nf = 0; nf < 4; nf++) {
        const int col = n0 + wn * 32 + nf * 8 + (lid & 3) * 2;
        const float bx = bias[col], by = bias[col + 1];
        #pragma unroll
        for (int f = 0; f < 4; f++) {
            const size_t r0 = (size_t)(m0 + wm * 64 + f * 16 + (lid >> 2));
            float* cp = C + r0 * H_ + col;
            float2 v0 = make_float2(acc[f][nf][0] + bx, acc[f][nf][1] + by);
            float2 v1 = make_float2(acc[f][nf][2] + bx, acc[f][nf][3] + by);
            *(float2*)cp = v0;
            *(float2*)(cp + (size_t)8 * H_) = v1;
        }
    }
}

// =================== Phase 2: persistent recurrent scan (R8 + tuned sync) =======
// 128 resident CTAs; CTA j owns output columns [j*8, j*8+8), Whh slice in smem.
// 8-batch x 4-col x 16-way-K-split register tile, scalar FFMA.
// vs R8: HCH=128 (8 chunks -> half the syncs), tree grid barrier, wx prefetch.
// 64 KB dynamic smem (1 CTA/SM) — size passed at launch (R14 bug fixed).
#define NCTA   128
#define CPC    8
#define T2     256
#define HCH    128
#define NCHUNK (H_ / HCH)   // 8
#define SCAN_SMEM ((CPC * H_ + B_ * HCH) * 4)   // 32KB + 32KB = 65536

__global__ __launch_bounds__(T2) void rnn_steps_kernel(
    const float* __restrict__ Whh,
    const float* __restrict__ Whh_b,
    float* __restrict__ y,      // [B,S,H], contains wx on entry
    float* __restrict__ hlast)  // [B,H] or nullptr
{
    extern __shared__ float dynsm[];
    float* sW = dynsm;              // 8 x 1024 (cols contiguous per row)
    float* sh = dynsm + CPC * H_;   // 64 x 128 chunk; reused as staging

    const int cta = blockIdx.x;
    const int tid = threadIdx.x;
    const int g0  = cta * CPC;
    const int grpid = cta >> 4;     // 8 groups of 16

    for (int v = tid; v < CPC * H_; v += T2)
        sW[v] = Whh[(size_t)g0 * H_ + v];

    const int ks = tid & 15;            // 16-way K split
    const int cg = (tid >> 4) & 1;      // 2 col groups of 4
    const int bg = tid >> 5;            // 8 batch groups of 8
    const int b0 = bg << 3;
    const int c0 = cg << 2;
    const float bi_fin = Whh_b[g0 + (tid & 7)];

    // finalize geometry (o = tid and tid+256)
    const int fb0 = tid >> 3, fgl = tid & 7;
    const int fb1 = (tid + T2) >> 3;

    for (int t = 0; t < S_; t++) {
        const float* hc = g_h[t & 1];
        float*       hn = g_h[(t & 1) ^ 1];

        // prefetch wx for finalize (independent of h; in flight all step)
        float wxa = y[((size_t)fb0 * S_ + t) * H_ + g0 + fgl];
        float wxb = y[((size_t)fb1 * S_ + t) * H_ + g0 + fgl];

        // prefetch chunk 0 of h (8 float4 per thread)
        float4 pf[8];
        #pragma unroll
        for (int i = 0; i < 8; i++) {
            int v = tid + i * T2;          // 0..2047 float4s = 64x128 floats
            int b  = v >> 5;
            int kl = (v & 31) << 2;
            pf[i] = *(const float4*)&hc[(size_t)b * H_ + kl];
        }

        float acc[8][4];
        #pragma unroll
        for (int j = 0; j < 8; j++)
            #pragma unroll
            for (int c = 0; c < 4; c++) acc[j][c] = 0.f;

        #pragma unroll 1
        for (int kc = 0; kc < NCHUNK; kc++) {
            __syncthreads();               // sh free for overwrite
            #pragma unroll
            for (int i = 0; i < 8; i++) {
                int v = tid + i * T2;
                int b  = v >> 5;
                int kl = (v & 31) << 2;
                *(float4*)&sh[b * HCH + kl] = pf[i];
            }
            if (kc + 1 < NCHUNK) {         // prefetch next chunk under compute
                #pragma unroll
                for (int i = 0; i < 8; i++) {
                    int v = tid + i * T2;
                    int b  = v >> 5;
                    int kl = (v & 31) << 2;
                    pf[i] = *(const float4*)&hc[(size_t)b * H_ + (kc + 1) * HCH + kl];
                }
            }
            __syncthreads();
            const int kgb = kc * HCH;
            #pragma unroll
            for (int i = 0; i < 2; i++) {
                const int klo = (i << 6) + (ks << 2);   // i*64 + ks*4
                float4 wv[4];
                #pragma unroll
                for (int c = 0; c < 4; c++)
                    wv[c] = *(const float4*)&sW[(c0 + c) * H_ + kgb + klo];
                #pragma unroll
                for (int j = 0; j < 8; j++) {
                    float4 hv = *(const float4*)&sh[(b0 + j) * HCH + klo];
                    #pragma unroll
                    for (int c = 0; c < 4; c++) {
                        acc[j][c] += hv.x * wv[c].x;
                        acc[j][c] += hv.y * wv[c].y;
                        acc[j][c] += hv.z * wv[c].z;
                        acc[j][c] += hv.w * wv[c].w;
                    }
                }
            }
        }

        // reduce 16-way K split (xor 1,2,4,8 within 16-lane groups)
        #pragma unroll
        for (int j = 0; j < 8; j++)
            #pragma unroll
            for (int c = 0; c < 4; c++) {
                float v = acc[j][c];
                v += __shfl_xor_sync(0xFFFFFFFFu, v, 1);
                v += __shfl_xor_sync(0xFFFFFFFFu, v, 2);
                v += __shfl_xor_sync(0xFFFFFFFFu, v, 4);
                v += __shfl_xor_sync(0xFFFFFFFFu, v, 8);
                acc[j][c] = v;
            }

        __syncthreads();                    // done reading sh (chunk data)
        if (ks == 0) {
            #pragma unroll
            for (int j = 0; j < 8; j++)
                #pragma unroll
                for (int c = 0; c < 4; c++)
                    sh[(b0 + j) * CPC + (c0 + c)] = acc[j][c];
        }
        __syncthreads();

        // finalize: tanh(wx + bias + sum), write y / h_next (/ h_last)
        {
            float v0 = tanhf(wxa + bi_fin + sh[tid]);
            float v1 = tanhf(wxb + bi_fin + sh[tid + T2]);
            y[((size_t)fb0 * S_ + t) * H_ + g0 + fgl] = v0;
            y[((size_t)fb1 * S_ + t) * H_ + g0 + fgl] = v1;
            hn[(size_t)fb0 * H_ + g0 + fgl] = v0;
            hn[(size_t)fb1 * H_ + g0 + fgl] = v1;
            if (hlast && t == S_ - 1) {
                hlast[(size_t)fb0 * H_ + g0 + fgl] = v0;
                hlast[(size_t)fb1 * H_ + g0 + fgl] = v1;
            }
        }

        // ---- two-level grid barrier: group counters -> root -> epoch flag ----
        __threadfence();
        __syncthreads();
        if (tid == 0) {
            unsigned old = atomicAdd(&g_cnt[grpid * 32], 1u);
            if (old == 16u * (unsigned)(t + 1) - 1u) {       // last in group
                unsigned r = atomicAdd(&g_root, 1u);
                if (r == 8u * (unsigned)(t + 1) - 1u) {      // last group
                    __threadfence();
                    g_epoch = (unsigned)(t + 1);
                }
            }
            while (g_epoch < (unsigned)(t + 1)) { __nanosleep(32); }
            __threadfence();
        }
        __syncthreads();
    }
}

// =================== launch ===================
extern "C" void kernel_launch(void* const* d_in, const int* in_sizes, int n_in,
                              void* d_out, int out_size) {
    (void)in_sizes; (void)n_in;
    const float* x     = (const float*)d_in[0];
    const float* h0    = (const float*)d_in[1];
    const float* Wih_w = (const float*)d_in[2];
    const float* Wih_b = (const float*)d_in[3];
    const float* Whh_w = (const float*)d_in[4];
    const float* Whh_b = (const float*)d_in[5];

    float* out   = (float*)d_out;
    float* y     = out;                              // [B,S,H]
    float* hlast = nullptr;                          // [B,H] appended if present
    const long long ybsh = (long long)B_ * S_ * H_;
    if ((long long)out_size >= ybsh + (long long)B_ * H_)
        hlast = out + ybsh;

    cudaFuncSetAttribute(rnn_steps_kernel, cudaFuncAttributeMaxDynamicSharedMemorySize,
                         SCAN_SMEM);

    // 1) init hidden state + barrier state
    init_kernel<<<(B_ * H_ + 255) / 256, 256>>>(h0);

    // 2) bf16 hi/lo split of x and Wih
    convert_x_kernel<<<(B_ * S_ * I_ / 4) / 256, 256>>>(x);
    convert_w_kernel<<<(H_ * I_ / 4) / 256, 256>>>(Wih_w);

    // 3) wx = x @ Wih^T + b via mma.sync bf16 split (3 passes), into y
    dim3 gg(H_ / 128, (B_ * S_) / 128);   // x-fastest: N-tiles share A panel in L2
    gemm_wx_mma<<<gg, 256>>>(Wih_b, y);

    // 4) persistent recurrent scan (128 resident CTAs, tree grid barrier)
    //    R14 bug fix: pass SCAN_SMEM at launch.
    rnn_steps_kernel<<<NCTA, T2, SCAN_SMEM>>>(Whh_w, Whh_b, y, hlast);
}